// round 15
// baseline (speedup 1.0000x reference)
#include <cuda_runtime.h>
#include <math.h>

// ---------------------------------------------------------------------------
// B=128; conv1: 3x100x100 -> 64x98x98 ->pool 49x49
// conv2: 64x49x49 -> 128x47x47 -> 23x23
// conv3: 128x23x23 -> 256x21x21 -> 10x10
// conv4: 256x10x10 -> 512x8x8 -> 4x4
// fc: 8192 -> 2048 -> 2048 -> 62 ; traj out (128, 4000, 2)
// ---------------------------------------------------------------------------

#define CBM 64
#define CBN 128
#define CBK 16

// Scratch (static device globals; allocation APIs are forbidden)
__device__ float g_h1[128u*64*49*49];
__device__ float g_c2[128u*128*47*47];
__device__ float g_h2[128u*128*23*23];
__device__ float g_c3[128u*256*21*21];
__device__ float g_h3[128u*256*10*10];
__device__ float g_c4[128u*512*8*8];
__device__ float g_h4[128u*8192];
__device__ float g_part1[16u*128*2048];
__device__ float g_fc1[128u*2048];
__device__ float g_part2[8u*128*2048];
__device__ float g_fc2[128u*2048];
__device__ float g_p[128u*62];

// ---- packed f32x2 helpers -------------------------------------------------
__device__ __forceinline__ unsigned long long pk2(float lo, float hi) {
    unsigned long long r;
    asm("mov.b64 %0, {%1, %2};" : "=l"(r) : "f"(lo), "f"(hi));
    return r;
}
__device__ __forceinline__ void fma2(unsigned long long &d, unsigned long long a,
                                     unsigned long long b) {
    asm("fma.rn.f32x2 %0, %1, %2, %0;" : "+l"(d) : "l"(a), "l"(b));
}
__device__ __forceinline__ void upk2(unsigned long long v, float &lo, float &hi) {
    asm("mov.b64 {%0, %1}, %2;" : "=f"(lo), "=f"(hi) : "l"(v));
}

// ---------------------------------------------------------------------------
// conv1 + pool + relu (direct). grid (128, 7), 256 threads.
// ---------------------------------------------------------------------------
__global__ __launch_bounds__(256)
void conv1_pool(const float* __restrict__ X, const float* __restrict__ W1,
                const float* __restrict__ B1, float* __restrict__ OUT)
{
    int b  = blockIdx.x;
    int rt = blockIdx.y;
    __shared__ float sin[3][16][100];
    __shared__ float sw[64*27];
    int tid = threadIdx.x;

    for (int i = tid; i < 64*27; i += 256) sw[i] = W1[i];
    int r0 = rt * 14;
    for (int i = tid; i < 3*16*100; i += 256) {
        int c = i / 1600; int rem = i - c*1600;
        int r = rem / 100; int col = rem - r*100;
        sin[c][r][col] = X[((size_t)b*3 + c)*10000 + (size_t)(r0 + r)*100 + col];
    }
    __syncthreads();

    for (int pos = tid; pos < 7*49; pos += 256) {
        int pr = pos / 49, px = pos - pr*49;
        int lr = pr*2, cx = px*2;
        float v[3][4][4];
        #pragma unroll
        for (int c = 0; c < 3; c++)
            #pragma unroll
            for (int ri = 0; ri < 4; ri++)
                #pragma unroll
                for (int ci = 0; ci < 4; ci++)
                    v[c][ri][ci] = sin[c][lr+ri][cx+ci];
        int py = rt*7 + pr;
        for (int oc = 0; oc < 64; oc++) {
            float a00=0.f, a01=0.f, a10=0.f, a11=0.f;
            const float* wp = &sw[oc*27];
            #pragma unroll
            for (int c = 0; c < 3; c++)
                #pragma unroll
                for (int ky = 0; ky < 3; ky++)
                    #pragma unroll
                    for (int kx = 0; kx < 3; kx++) {
                        float w = wp[c*9 + ky*3 + kx];
                        a00 += w * v[c][ky  ][kx  ];
                        a01 += w * v[c][ky  ][kx+1];
                        a10 += w * v[c][ky+1][kx  ];
                        a11 += w * v[c][ky+1][kx+1];
                    }
            float m = fmaxf(fmaxf(a00, a01), fmaxf(a10, a11)) + B1[oc];
            OUT[(((size_t)b*64 + oc)*49 + py)*49 + px] = fmaxf(m, 0.f);
        }
    }
}

// ---------------------------------------------------------------------------
// Implicit-GEMM conv. BM=64, BN=128, BK=16, 128 threads, 4 CTAs/SM.
// A stored DUPLICATED in smem ([a,a] pairs) so the FFMA2 mainloop has
// zero pack-movs: per kk = 32 FFMA2 + 6 LDS.128.
// ---------------------------------------------------------------------------
__global__ __launch_bounds__(128, 4)
void conv_gemm(const float* __restrict__ W, const float* __restrict__ IN,
               const float* __restrict__ bias, float* __restrict__ OUT,
               int M, int K, int IC, int IH, int IW, int OH, int OW, int G)
{
    int OHW = OH * OW;
    int Ntot = G * OHW;
    int z  = blockIdx.z;
    int m0 = blockIdx.y * CBM, n0 = blockIdx.x * CBN;
    int tid = threadIdx.x;

    __shared__ __align__(16) float Ad[2][CBK][2*CBM];   // duplicated pairs
    __shared__ __align__(16) float Bs[2][CBK][CBN];
    __shared__ __align__(16) int koff[2304];

    int am = tid & 63;           // A row
    int aq = tid >> 6;           // A k-half (0/1)
    int bn = tid & 127;          // B col; loads all 16 k rows

    // warp-local 4x8 thread grid -> single-wavefront fragment loads
    int lane = tid & 31, w = tid >> 5;
    int txg = ((w & 1) << 3) | (lane & 7);    // 0..15
    int tyg = ((w >> 1) << 2) | (lane >> 3);  // 0..7
    int fm = tyg * 4;
    int fn = txg * 4;

    for (int k = tid; k < K; k += 128) {
        int ic = k / 9; int r = k - ic*9; int ky = r / 3; int kx = r - ky*3;
        koff[k] = ic*IH*IW + ky*IW + kx;
    }

    int n_g  = n0 + bn;
    bool nvalid = n_g < Ntot;
    int img = nvalid ? (n_g / OHW) : 0;
    int sp  = nvalid ? (n_g - img * OHW) : 0;
    int ny  = sp / OW, nx = sp - ny * OW;
    const float* inp = IN + ((size_t)(z*G + img)) * IC * IH * IW + (size_t)ny * IW + nx;
    const float* wrow = W + (size_t)(m0 + am) * K;

    float4 aR0, aR1; float bR[16];
    unsigned long long acc2[8][4] = {};   // 8 rows x 4 col-pairs
    int nk = K / CBK;

    __syncthreads();   // LUT ready

    // stage 0 global->smem
    {
        aR0 = *reinterpret_cast<const float4*>(wrow + aq*8);
        aR1 = *reinterpret_cast<const float4*>(wrow + aq*8 + 4);
        #pragma unroll
        for (int jj = 0; jj < 4; jj++) {
            int4 o = *reinterpret_cast<const int4*>(&koff[jj*4]);
            if (nvalid) {
                bR[jj*4+0]=inp[o.x]; bR[jj*4+1]=inp[o.y];
                bR[jj*4+2]=inp[o.z]; bR[jj*4+3]=inp[o.w];
            } else {
                bR[jj*4+0]=0.f; bR[jj*4+1]=0.f; bR[jj*4+2]=0.f; bR[jj*4+3]=0.f;
            }
        }
        int ab = aq*8;
        float av[8] = {aR0.x, aR0.y, aR0.z, aR0.w, aR1.x, aR1.y, aR1.z, aR1.w};
        #pragma unroll
        for (int j = 0; j < 8; j++)
            *reinterpret_cast<unsigned long long*>(&Ad[0][ab+j][2*am]) = pk2(av[j], av[j]);
        #pragma unroll
        for (int j = 0; j < 16; j++) Bs[0][j][bn] = bR[j];
    }
    __syncthreads();

    for (int t = 0; t < nk; t++) {
        int cur = t & 1;
        if (t + 1 < nk) {
            int k0 = (t + 1) * CBK;
            aR0 = *reinterpret_cast<const float4*>(wrow + k0 + aq*8);
            aR1 = *reinterpret_cast<const float4*>(wrow + k0 + aq*8 + 4);
            #pragma unroll
            for (int jj = 0; jj < 4; jj++) {
                int4 o = *reinterpret_cast<const int4*>(&koff[k0 + jj*4]);
                if (nvalid) {
                    bR[jj*4+0]=inp[o.x]; bR[jj*4+1]=inp[o.y];
                    bR[jj*4+2]=inp[o.z]; bR[jj*4+3]=inp[o.w];
                } else {
                    bR[jj*4+0]=0.f; bR[jj*4+1]=0.f; bR[jj*4+2]=0.f; bR[jj*4+3]=0.f;
                }
            }
        }
        #pragma unroll
        for (int kk = 0; kk < CBK; kk++) {
            ulonglong2 apA = *reinterpret_cast<const ulonglong2*>(&Ad[cur][kk][2*fm]);
            ulonglong2 apB = *reinterpret_cast<const ulonglong2*>(&Ad[cur][kk][2*fm + 4]);
            ulonglong2 apC = *reinterpret_cast<const ulonglong2*>(&Ad[cur][kk][64 + 2*fm]);
            ulonglong2 apD = *reinterpret_cast<const ulonglong2*>(&Ad[cur][kk][64 + 2*fm + 4]);
            ulonglong2 bp0 = *reinterpret_cast<const ulonglong2*>(&Bs[cur][kk][fn]);
            ulonglong2 bp1 = *reinterpret_cast<const ulonglong2*>(&Bs[cur][kk][fn + 64]);
            unsigned long long ai[8] = {apA.x, apA.y, apB.x, apB.y,
                                        apC.x, apC.y, apD.x, apD.y};
            unsigned long long bb[4] = {bp0.x, bp0.y, bp1.x, bp1.y};
            #pragma unroll
            for (int i = 0; i < 8; i++)
                #pragma unroll
                for (int j = 0; j < 4; j++)
                    fma2(acc2[i][j], ai[i], bb[j]);
        }
        if (t + 1 < nk) {
            int nxt = cur ^ 1;
            int ab = aq*8;
            float av[8] = {aR0.x, aR0.y, aR0.z, aR0.w, aR1.x, aR1.y, aR1.z, aR1.w};
            #pragma unroll
            for (int j = 0; j < 8; j++)
                *reinterpret_cast<unsigned long long*>(&Ad[nxt][ab+j][2*am]) = pk2(av[j], av[j]);
            #pragma unroll
            for (int j = 0; j < 16; j++) Bs[nxt][j][bn] = bR[j];
        }
        __syncthreads();
    }

    #pragma unroll
    for (int i = 0; i < 8; i++) {
        int m = m0 + (i < 4 ? fm + i : 32 + fm + (i - 4));
        float bv = bias[m];
        float av[8];
        upk2(acc2[i][0], av[0], av[1]);
        upk2(acc2[i][1], av[2], av[3]);
        upk2(acc2[i][2], av[4], av[5]);
        upk2(acc2[i][3], av[6], av[7]);
        #pragma unroll
        for (int j = 0; j < 8; j++) {
            int n = n0 + (j < 4 ? fn + j : 64 + fn + (j - 4));
            if (n >= Ntot) continue;
            int img2 = n / OHW; int sp2 = n - img2 * OHW;
            OUT[((size_t)(z*G + img2)*M + m)*OHW + sp2] = av[j] + bv;
        }
    }
}

// ---------------------------------------------------------------------------
// maxpool 2x2 stride 2 + relu
// ---------------------------------------------------------------------------
__global__ void pool_relu(const float* __restrict__ in, float* __restrict__ out,
                          int IH, int IW, int OH, int OW, int total)
{
    int idx = blockIdx.x * blockDim.x + threadIdx.x;
    if (idx >= total) return;
    int x = idx % OW;
    int y = (idx / OW) % OH;
    int bc = idx / (OH * OW);
    const float* p = in + ((size_t)bc * IH + 2*y) * IW + 2*x;
    float m = fmaxf(fmaxf(p[0], p[1]), fmaxf(p[IW], p[IW+1]));
    out[idx] = fmaxf(m, 0.f);
}

// ---------------------------------------------------------------------------
// FC GEMM, split-K, BM=64, BN=128, BK=16, 128 threads, A-dup + FFMA2.
// ---------------------------------------------------------------------------
__global__ __launch_bounds__(128, 4)
void fc_gemm(const float* __restrict__ A, const float* __restrict__ Bm,
             float* __restrict__ Cp, int N, int K, int KC)
{
    int z = blockIdx.z;
    int m0 = blockIdx.y * CBM;
    int n0 = blockIdx.x * CBN;
    int k0base = z * KC;
    int tid = threadIdx.x;

    __shared__ __align__(16) float Ad[2][CBK][2*CBM];
    __shared__ __align__(16) float Bs[2][CBK][CBN];

    int am = tid & 63; int aq = tid >> 6;
    int bk = tid >> 5; int bn4 = (tid & 31) * 4;

    int lane = tid & 31, w = tid >> 5;
    int txg = ((w & 1) << 3) | (lane & 7);
    int tyg = ((w >> 1) << 2) | (lane >> 3);
    int fm = tyg * 4, fn = txg * 4;

    float4 aR0, aR1, bV0, bV1, bV2, bV3;
    unsigned long long acc2[8][4] = {};
    int nk = KC / CBK;

    const float* arow = A + (size_t)(m0 + am) * K;

    aR0 = *reinterpret_cast<const float4*>(arow + k0base + aq*8);
    aR1 = *reinterpret_cast<const float4*>(arow + k0base + aq*8 + 4);
    bV0 = *reinterpret_cast<const float4*>(Bm + (size_t)(k0base + bk)      * N + n0 + bn4);
    bV1 = *reinterpret_cast<const float4*>(Bm + (size_t)(k0base + bk + 4)  * N + n0 + bn4);
    bV2 = *reinterpret_cast<const float4*>(Bm + (size_t)(k0base + bk + 8)  * N + n0 + bn4);
    bV3 = *reinterpret_cast<const float4*>(Bm + (size_t)(k0base + bk + 12) * N + n0 + bn4);
    {
        int ab = aq*8;
        float av[8] = {aR0.x, aR0.y, aR0.z, aR0.w, aR1.x, aR1.y, aR1.z, aR1.w};
        #pragma unroll
        for (int j = 0; j < 8; j++)
            *reinterpret_cast<unsigned long long*>(&Ad[0][ab+j][2*am]) = pk2(av[j], av[j]);
        *reinterpret_cast<float4*>(&Bs[0][bk][bn4])    = bV0;
        *reinterpret_cast<float4*>(&Bs[0][bk+4][bn4])  = bV1;
        *reinterpret_cast<float4*>(&Bs[0][bk+8][bn4])  = bV2;
        *reinterpret_cast<float4*>(&Bs[0][bk+12][bn4]) = bV3;
    }
    __syncthreads();

    for (int t = 0; t < nk; t++) {
        int cur = t & 1;
        if (t + 1 < nk) {
            int k0 = k0base + (t + 1) * CBK;
            aR0 = *reinterpret_cast<const float4*>(arow + k0 + aq*8);
            aR1 = *reinterpret_cast<const float4*>(arow + k0 + aq*8 + 4);
            bV0 = *reinterpret_cast<const float4*>(Bm + (size_t)(k0 + bk)      * N + n0 + bn4);
            bV1 = *reinterpret_cast<const float4*>(Bm + (size_t)(k0 + bk + 4)  * N + n0 + bn4);
            bV2 = *reinterpret_cast<const float4*>(Bm + (size_t)(k0 + bk + 8)  * N + n0 + bn4);
            bV3 = *reinterpret_cast<const float4*>(Bm + (size_t)(k0 + bk + 12) * N + n0 + bn4);
        }
        #pragma unroll
        for (int kk = 0; kk < CBK; kk++) {
            ulonglong2 apA = *reinterpret_cast<const ulonglong2*>(&Ad[cur][kk][2*fm]);
            ulonglong2 apB = *reinterpret_cast<const ulonglong2*>(&Ad[cur][kk][2*fm + 4]);
            ulonglong2 apC = *reinterpret_cast<const ulonglong2*>(&Ad[cur][kk][64 + 2*fm]);
            ulonglong2 apD = *reinterpret_cast<const ulonglong2*>(&Ad[cur][kk][64 + 2*fm + 4]);
            ulonglong2 bp0 = *reinterpret_cast<const ulonglong2*>(&Bs[cur][kk][fn]);
            ulonglong2 bp1 = *reinterpret_cast<const ulonglong2*>(&Bs[cur][kk][fn + 64]);
            unsigned long long ai[8] = {apA.x, apA.y, apB.x, apB.y,
                                        apC.x, apC.y, apD.x, apD.y};
            unsigned long long bb[4] = {bp0.x, bp0.y, bp1.x, bp1.y};
            #pragma unroll
            for (int i = 0; i < 8; i++)
                #pragma unroll
                for (int j = 0; j < 4; j++)
                    fma2(acc2[i][j], ai[i], bb[j]);
        }
        if (t + 1 < nk) {
            int nxt = cur ^ 1;
            int ab = aq*8;
            float av[8] = {aR0.x, aR0.y, aR0.z, aR0.w, aR1.x, aR1.y, aR1.z, aR1.w};
            #pragma unroll
            for (int j = 0; j < 8; j++)
                *reinterpret_cast<unsigned long long*>(&Ad[nxt][ab+j][2*am]) = pk2(av[j], av[j]);
            *reinterpret_cast<float4*>(&Bs[nxt][bk][bn4])    = bV0;
            *reinterpret_cast<float4*>(&Bs[nxt][bk+4][bn4])  = bV1;
            *reinterpret_cast<float4*>(&Bs[nxt][bk+8][bn4])  = bV2;
            *reinterpret_cast<float4*>(&Bs[nxt][bk+12][bn4]) = bV3;
        }
        __syncthreads();
    }

    float* outp = Cp + (size_t)z * 128 * N;
    #pragma unroll
    for (int i = 0; i < 8; i++) {
        int rm = m0 + (i < 4 ? fm + i : 32 + fm + (i - 4));
        float av[8];
        upk2(acc2[i][0], av[0], av[1]);
        upk2(acc2[i][1], av[2], av[3]);
        upk2(acc2[i][2], av[4], av[5]);
        upk2(acc2[i][3], av[6], av[7]);
        float4 s0 = make_float4(av[0], av[1], av[2], av[3]);
        float4 s1 = make_float4(av[4], av[5], av[6], av[7]);
        *reinterpret_cast<float4*>(&outp[(size_t)rm*N + n0 + fn     ]) = s0;
        *reinterpret_cast<float4*>(&outp[(size_t)rm*N + n0 + 64 + fn]) = s1;
    }
}

// sum split-K partials + bias + tanh
__global__ void fc_reduce_tanh(const float* __restrict__ part, const float* __restrict__ bias,
                               float* __restrict__ out, int MN, int N, int S)
{
    int idx = blockIdx.x * blockDim.x + threadIdx.x;
    if (idx >= MN) return;
    float s = 0.f;
    for (int i = 0; i < S; i++) s += part[(size_t)i * MN + idx];
    out[idx] = tanhf(s + bias[idx % N]);
}

// fc3: P[b][n] = sum_k H[b][k] * W[k][n] + bias[n]   (N=62)
__global__ void fc3_kernel(const float* __restrict__ H, const float* __restrict__ W,
                           const float* __restrict__ Bb, float* __restrict__ P)
{
    __shared__ float hs[2048];
    int b = blockIdx.x, tid = threadIdx.x;  // 64 threads
    for (int i = tid; i < 2048; i += 64) hs[i] = H[(size_t)b*2048 + i];
    __syncthreads();
    if (tid < 62) {
        float acc = Bb[tid];
        #pragma unroll 4
        for (int k = 0; k < 2048; k++) acc += hs[k] * W[(size_t)k*62 + tid];
        P[b*62 + tid] = acc;
    }
}

// trajectory assembly: out (128, 20*200, 2)
__global__ void traj_kernel(const float* __restrict__ P, const float* __restrict__ TD,
                            float* __restrict__ OUT)
{
    int b = blockIdx.x, tid = threadIdx.x;  // 256 threads
    __shared__ int   sidx[20];
    __shared__ float ssc[20][2];
    __shared__ float soff[20][2];
    __shared__ float sst[20][2];

    if (tid < 20) {
        float s0 = P[b*62 + 2 + tid*3];
        float s1 = P[b*62 + 3 + tid*3];
        float s2 = P[b*62 + 4 + tid*3];
        int idx = (int)fminf(fmaxf(rintf(s0), 0.f), 999.f);
        sidx[tid] = idx;
        ssc[tid][0] = s1; ssc[tid][1] = s2;
        soff[tid][0] = TD[idx*400 + 199*2 + 0] * s1;
        soff[tid][1] = TD[idx*400 + 199*2 + 1] * s2;
    }
    __syncthreads();
    if (tid == 0) {
        float cx = P[b*62 + 0], cy = P[b*62 + 1];
        for (int s = 0; s < 20; s++) {
            sst[s][0] = cx; sst[s][1] = cy;
            cx += soff[s][0]; cy += soff[s][1];
        }
    }
    __syncthreads();
    for (int e = tid; e < 20*200*2; e += 256) {
        int s = e / 400; int r = e - s*400;
        int c = r & 1;
        OUT[(size_t)b*8000 + e] = TD[sidx[s]*400 + r] * ssc[s][c] + sst[s][c];
    }
}

// ---------------------------------------------------------------------------
extern "C" void kernel_launch(void* const* d_in, const int* in_sizes, int n_in,
                              void* d_out, int out_size)
{
    const float* x   = (const float*)d_in[0];
    const float* w1  = (const float*)d_in[1];
    const float* b1  = (const float*)d_in[2];
    const float* w2  = (const float*)d_in[3];
    const float* b2  = (const float*)d_in[4];
    const float* w3  = (const float*)d_in[5];
    const float* b3  = (const float*)d_in[6];
    const float* w4  = (const float*)d_in[7];
    const float* b4  = (const float*)d_in[8];
    const float* fw1 = (const float*)d_in[9];
    const float* fb1 = (const float*)d_in[10];
    const float* fw2 = (const float*)d_in[11];
    const float* fb2 = (const float*)d_in[12];
    const float* fw3 = (const float*)d_in[13];
    const float* fb3 = (const float*)d_in[14];
    const float* td  = (const float*)d_in[15];

    float *h1, *c2, *h2, *c3, *h3, *c4, *h4, *p1, *f1, *p2, *f2, *pp;
    cudaGetSymbolAddress((void**)&h1, g_h1);
    cudaGetSymbolAddress((void**)&c2, g_c2);
    cudaGetSymbolAddress((void**)&h2, g_h2);
    cudaGetSymbolAddress((void**)&c3, g_c3);
    cudaGetSymbolAddress((void**)&h3, g_h3);
    cudaGetSymbolAddress((void**)&c4, g_c4);
    cudaGetSymbolAddress((void**)&h4, g_h4);
    cudaGetSymbolAddress((void**)&p1, g_part1);
    cudaGetSymbolAddress((void**)&f1, g_fc1);
    cudaGetSymbolAddress((void**)&p2, g_part2);
    cudaGetSymbolAddress((void**)&f2, g_fc2);
    cudaGetSymbolAddress((void**)&pp, g_p);

    // conv1 (fused pool+relu)
    conv1_pool<<<dim3(128, 7), 256>>>(x, w1, b1, h1);

    // conv2: M=128 (2 m-blocks), K=576, N=2209 per image, G=1
    conv_gemm<<<dim3(18, 2, 128), 128>>>(w2, h1, b2, c2, 128, 576, 64, 49, 49, 47, 47, 1);
    pool_relu<<<(8667136 + 255)/256, 256>>>(c2, h2, 47, 47, 23, 23, 8667136);

    // conv3: M=256 (4 m-blocks), K=1152, G=128 -> N=56448 = 441 exact tiles
    conv_gemm<<<dim3(441, 4, 1), 128>>>(w3, h2, b3, c3, 256, 1152, 128, 23, 23, 21, 21, 128);
    pool_relu<<<(3276800 + 255)/256, 256>>>(c3, h3, 21, 21, 10, 10, 3276800);

    // conv4: M=512 (8 m-blocks), K=2304, G=128 -> N=8192 = 64 exact tiles
    conv_gemm<<<dim3(64, 8, 1), 128>>>(w4, h3, b4, c4, 512, 2304, 256, 10, 10, 8, 8, 128);
    pool_relu<<<(1048576 + 255)/256, 256>>>(c4, h4, 8, 8, 4, 4, 1048576);

    // fc1: 128x8192 @ 8192x2048, split-K=16 (512 blocks)
    fc_gemm<<<dim3(16, 2, 16), 128>>>(h4, fw1, p1, 2048, 8192, 512);
    fc_reduce_tanh<<<(262144 + 255)/256, 256>>>(p1, fb1, f1, 262144, 2048, 16);

    // fc2: 128x2048 @ 2048x2048, split-K=8 (256 blocks)
    fc_gemm<<<dim3(16, 2, 8), 128>>>(f1, fw2, p2, 2048, 2048, 256);
    fc_reduce_tanh<<<(262144 + 255)/256, 256>>>(p2, fb2, f2, 262144, 2048, 8);

    // fc3: 2048 -> 62
    fc3_kernel<<<128, 64>>>(f2, fw3, fb3, pp);

    // trajectory assembly -> d_out (128*4000*2 floats)
    traj_kernel<<<128, 256>>>(pp, td, (float*)d_out);
}

// round 16
// speedup vs baseline: 1.1734x; 1.1734x over previous
#include <cuda_runtime.h>
#include <math.h>

// ---------------------------------------------------------------------------
// B=128; conv1: 3x100x100 -> 64x98x98 ->pool 49x49
// conv2: 64x49x49 -> 128x47x47 -> 23x23
// conv3: 128x23x23 -> 256x21x21 -> 10x10
// conv4: 256x10x10 -> 512x8x8 -> 4x4
// fc: 8192 -> 2048 -> 2048 -> 62 ; traj out (128, 4000, 2)
// ---------------------------------------------------------------------------

#define CBM 64
#define CBN 128
#define CBK 16

// Scratch (static device globals; allocation APIs are forbidden)
__device__ float g_h1[128u*64*49*49];
__device__ float g_c2[128u*128*47*47];
__device__ float g_h2[128u*128*23*23];
__device__ float g_c3[128u*256*21*21];
__device__ float g_h3[128u*256*10*10];
__device__ float g_c4[128u*512*8*8];
__device__ float g_h4[128u*8192];
__device__ float g_part1[16u*128*2048];
__device__ float g_fc1[128u*2048];
__device__ float g_part2[8u*128*2048];
__device__ float g_fc2[128u*2048];
__device__ float g_p[128u*62];

// ---- packed f32x2 helpers -------------------------------------------------
__device__ __forceinline__ unsigned long long pk2(float lo, float hi) {
    unsigned long long r;
    asm("mov.b64 %0, {%1, %2};" : "=l"(r) : "f"(lo), "f"(hi));
    return r;
}
__device__ __forceinline__ void fma2(unsigned long long &d, unsigned long long a,
                                     unsigned long long b) {
    asm("fma.rn.f32x2 %0, %1, %2, %0;" : "+l"(d) : "l"(a), "l"(b));
}
__device__ __forceinline__ void upk2(unsigned long long v, float &lo, float &hi) {
    asm("mov.b64 {%0, %1}, %2;" : "=f"(lo), "=f"(hi) : "l"(v));
}

// ---------------------------------------------------------------------------
// conv1 + pool + relu (direct). grid (128, 7), 256 threads.
// ---------------------------------------------------------------------------
__global__ __launch_bounds__(256)
void conv1_pool(const float* __restrict__ X, const float* __restrict__ W1,
                const float* __restrict__ B1, float* __restrict__ OUT)
{
    int b  = blockIdx.x;
    int rt = blockIdx.y;
    __shared__ float sin[3][16][100];
    __shared__ float sw[64*27];
    int tid = threadIdx.x;

    for (int i = tid; i < 64*27; i += 256) sw[i] = W1[i];
    int r0 = rt * 14;
    for (int i = tid; i < 3*16*100; i += 256) {
        int c = i / 1600; int rem = i - c*1600;
        int r = rem / 100; int col = rem - r*100;
        sin[c][r][col] = X[((size_t)b*3 + c)*10000 + (size_t)(r0 + r)*100 + col];
    }
    __syncthreads();

    for (int pos = tid; pos < 7*49; pos += 256) {
        int pr = pos / 49, px = pos - pr*49;
        int lr = pr*2, cx = px*2;
        float v[3][4][4];
        #pragma unroll
        for (int c = 0; c < 3; c++)
            #pragma unroll
            for (int ri = 0; ri < 4; ri++)
                #pragma unroll
                for (int ci = 0; ci < 4; ci++)
                    v[c][ri][ci] = sin[c][lr+ri][cx+ci];
        int py = rt*7 + pr;
        for (int oc = 0; oc < 64; oc++) {
            float a00=0.f, a01=0.f, a10=0.f, a11=0.f;
            const float* wp = &sw[oc*27];
            #pragma unroll
            for (int c = 0; c < 3; c++)
                #pragma unroll
                for (int ky = 0; ky < 3; ky++)
                    #pragma unroll
                    for (int kx = 0; kx < 3; kx++) {
                        float w = wp[c*9 + ky*3 + kx];
                        a00 += w * v[c][ky  ][kx  ];
                        a01 += w * v[c][ky  ][kx+1];
                        a10 += w * v[c][ky+1][kx  ];
                        a11 += w * v[c][ky+1][kx+1];
                    }
            float m = fmaxf(fmaxf(a00, a01), fmaxf(a10, a11)) + B1[oc];
            OUT[(((size_t)b*64 + oc)*49 + py)*49 + px] = fmaxf(m, 0.f);
        }
    }
}

// ---------------------------------------------------------------------------
// Implicit-GEMM conv. BM=64, BN=128, BK=16, 128 threads, 4 CTAs/SM.
// LDG->STS staging, FFMA2 inner product, direct ulonglong2 B-fragment reads.
// N flattened across images (G images per z-block).
// ---------------------------------------------------------------------------
__global__ __launch_bounds__(128, 4)
void conv_gemm(const float* __restrict__ W, const float* __restrict__ IN,
               const float* __restrict__ bias, float* __restrict__ OUT,
               int M, int K, int IC, int IH, int IW, int OH, int OW, int G)
{
    int OHW = OH * OW;
    int Ntot = G * OHW;
    int z  = blockIdx.z;
    int m0 = blockIdx.y * CBM, n0 = blockIdx.x * CBN;
    int tid = threadIdx.x;

    __shared__ __align__(16) float As[2][CBK][CBM];
    __shared__ __align__(16) float Bs[2][CBK][CBN];
    __shared__ __align__(16) int koff[2304];

    int am = tid & 63;           // A row
    int aq = tid >> 6;           // A k-half (0/1)
    int bn = tid & 127;          // B col; loads all 16 k rows

    // warp-local 4x8 thread grid -> single-wavefront fragment loads
    int lane = tid & 31, w = tid >> 5;
    int txg = ((w & 1) << 3) | (lane & 7);    // 0..15
    int tyg = ((w >> 1) << 2) | (lane >> 3);  // 0..7
    int fm = tyg * 4;
    int fn = txg * 4;

    for (int k = tid; k < K; k += 128) {
        int ic = k / 9; int r = k - ic*9; int ky = r / 3; int kx = r - ky*3;
        koff[k] = ic*IH*IW + ky*IW + kx;
    }

    int n_g  = n0 + bn;
    bool nvalid = n_g < Ntot;
    int img = nvalid ? (n_g / OHW) : 0;
    int sp  = nvalid ? (n_g - img * OHW) : 0;
    int ny  = sp / OW, nx = sp - ny * OW;
    const float* inp = IN + ((size_t)(z*G + img)) * IC * IH * IW + (size_t)ny * IW + nx;
    const float* wrow = W + (size_t)(m0 + am) * K;

    float4 aR0, aR1; float bR[16];
    unsigned long long acc2[8][4] = {};   // 8 rows x 4 col-pairs
    int nk = K / CBK;

    __syncthreads();   // LUT ready

    // stage 0 global->smem
    {
        aR0 = *reinterpret_cast<const float4*>(wrow + aq*8);
        aR1 = *reinterpret_cast<const float4*>(wrow + aq*8 + 4);
        #pragma unroll
        for (int jj = 0; jj < 4; jj++) {
            int4 o = *reinterpret_cast<const int4*>(&koff[jj*4]);
            if (nvalid) {
                bR[jj*4+0]=inp[o.x]; bR[jj*4+1]=inp[o.y];
                bR[jj*4+2]=inp[o.z]; bR[jj*4+3]=inp[o.w];
            } else {
                bR[jj*4+0]=0.f; bR[jj*4+1]=0.f; bR[jj*4+2]=0.f; bR[jj*4+3]=0.f;
            }
        }
        int ab = aq*8;
        As[0][ab+0][am]=aR0.x; As[0][ab+1][am]=aR0.y; As[0][ab+2][am]=aR0.z; As[0][ab+3][am]=aR0.w;
        As[0][ab+4][am]=aR1.x; As[0][ab+5][am]=aR1.y; As[0][ab+6][am]=aR1.z; As[0][ab+7][am]=aR1.w;
        #pragma unroll
        for (int j = 0; j < 16; j++) Bs[0][j][bn] = bR[j];
    }
    __syncthreads();

    for (int t = 0; t < nk; t++) {
        int cur = t & 1;
        if (t + 1 < nk) {
            int k0 = (t + 1) * CBK;
            aR0 = *reinterpret_cast<const float4*>(wrow + k0 + aq*8);
            aR1 = *reinterpret_cast<const float4*>(wrow + k0 + aq*8 + 4);
            #pragma unroll
            for (int jj = 0; jj < 4; jj++) {
                int4 o = *reinterpret_cast<const int4*>(&koff[k0 + jj*4]);
                if (nvalid) {
                    bR[jj*4+0]=inp[o.x]; bR[jj*4+1]=inp[o.y];
                    bR[jj*4+2]=inp[o.z]; bR[jj*4+3]=inp[o.w];
                } else {
                    bR[jj*4+0]=0.f; bR[jj*4+1]=0.f; bR[jj*4+2]=0.f; bR[jj*4+3]=0.f;
                }
            }
        }
        #pragma unroll
        for (int kk = 0; kk < CBK; kk++) {
            float4 a0 = *reinterpret_cast<const float4*>(&As[cur][kk][fm]);
            float4 a1 = *reinterpret_cast<const float4*>(&As[cur][kk][fm + 32]);
            ulonglong2 bp0 = *reinterpret_cast<const ulonglong2*>(&Bs[cur][kk][fn]);
            ulonglong2 bp1 = *reinterpret_cast<const ulonglong2*>(&Bs[cur][kk][fn + 64]);
            unsigned long long bb[4] = {bp0.x, bp0.y, bp1.x, bp1.y};
            float a[8] = {a0.x, a0.y, a0.z, a0.w, a1.x, a1.y, a1.z, a1.w};
            #pragma unroll
            for (int i = 0; i < 8; i++) {
                unsigned long long ai = pk2(a[i], a[i]);
                #pragma unroll
                for (int j = 0; j < 4; j++)
                    fma2(acc2[i][j], ai, bb[j]);
            }
        }
        if (t + 1 < nk) {
            int nxt = cur ^ 1;
            int ab = aq*8;
            As[nxt][ab+0][am]=aR0.x; As[nxt][ab+1][am]=aR0.y; As[nxt][ab+2][am]=aR0.z; As[nxt][ab+3][am]=aR0.w;
            As[nxt][ab+4][am]=aR1.x; As[nxt][ab+5][am]=aR1.y; As[nxt][ab+6][am]=aR1.z; As[nxt][ab+7][am]=aR1.w;
            #pragma unroll
            for (int j = 0; j < 16; j++) Bs[nxt][j][bn] = bR[j];
        }
        __syncthreads();
    }

    #pragma unroll
    for (int i = 0; i < 8; i++) {
        int m = m0 + (i < 4 ? fm + i : 32 + fm + (i - 4));
        float bv = bias[m];
        float av[8];
        upk2(acc2[i][0], av[0], av[1]);
        upk2(acc2[i][1], av[2], av[3]);
        upk2(acc2[i][2], av[4], av[5]);
        upk2(acc2[i][3], av[6], av[7]);
        #pragma unroll
        for (int j = 0; j < 8; j++) {
            int n = n0 + (j < 4 ? fn + j : 64 + fn + (j - 4));
            if (n >= Ntot) continue;
            int img2 = n / OHW; int sp2 = n - img2 * OHW;
            OUT[((size_t)(z*G + img2)*M + m)*OHW + sp2] = av[j] + bv;
        }
    }
}

// ---------------------------------------------------------------------------
// maxpool 2x2 stride 2 + relu
// ---------------------------------------------------------------------------
__global__ void pool_relu(const float* __restrict__ in, float* __restrict__ out,
                          int IH, int IW, int OH, int OW, int total)
{
    int idx = blockIdx.x * blockDim.x + threadIdx.x;
    if (idx >= total) return;
    int x = idx % OW;
    int y = (idx / OW) % OH;
    int bc = idx / (OH * OW);
    const float* p = in + ((size_t)bc * IH + 2*y) * IW + 2*x;
    float m = fmaxf(fmaxf(p[0], p[1]), fmaxf(p[IW], p[IW+1]));
    out[idx] = fmaxf(m, 0.f);
}

// ---------------------------------------------------------------------------
// FC GEMM, split-K, BM=64, BN=128, BK=16, 128 threads (R12 structure + FFMA2).
// ---------------------------------------------------------------------------
__global__ __launch_bounds__(128, 4)
void fc_gemm(const float* __restrict__ A, const float* __restrict__ Bm,
             float* __restrict__ Cp, int N, int K, int KC)
{
    int z = blockIdx.z;
    int m0 = blockIdx.y * CBM;
    int n0 = blockIdx.x * CBN;
    int k0base = z * KC;
    int tid = threadIdx.x;

    __shared__ __align__(16) float As[2][CBK][CBM];
    __shared__ __align__(16) float Bs[2][CBK][CBN];

    int am = tid & 63; int aq = tid >> 6;
    int bk = tid >> 5; int bn4 = (tid & 31) * 4;

    int lane = tid & 31, w = tid >> 5;
    int txg = ((w & 1) << 3) | (lane & 7);
    int tyg = ((w >> 1) << 2) | (lane >> 3);
    int fm = tyg * 4, fn = txg * 4;

    float4 aR0, aR1, bV0, bV1, bV2, bV3;
    unsigned long long acc2[8][4] = {};
    int nk = KC / CBK;

    const float* arow = A + (size_t)(m0 + am) * K;

    aR0 = *reinterpret_cast<const float4*>(arow + k0base + aq*8);
    aR1 = *reinterpret_cast<const float4*>(arow + k0base + aq*8 + 4);
    bV0 = *reinterpret_cast<const float4*>(Bm + (size_t)(k0base + bk)      * N + n0 + bn4);
    bV1 = *reinterpret_cast<const float4*>(Bm + (size_t)(k0base + bk + 4)  * N + n0 + bn4);
    bV2 = *reinterpret_cast<const float4*>(Bm + (size_t)(k0base + bk + 8)  * N + n0 + bn4);
    bV3 = *reinterpret_cast<const float4*>(Bm + (size_t)(k0base + bk + 12) * N + n0 + bn4);
    {
        int ab = aq*8;
        As[0][ab+0][am]=aR0.x; As[0][ab+1][am]=aR0.y; As[0][ab+2][am]=aR0.z; As[0][ab+3][am]=aR0.w;
        As[0][ab+4][am]=aR1.x; As[0][ab+5][am]=aR1.y; As[0][ab+6][am]=aR1.z; As[0][ab+7][am]=aR1.w;
        *reinterpret_cast<float4*>(&Bs[0][bk][bn4])    = bV0;
        *reinterpret_cast<float4*>(&Bs[0][bk+4][bn4])  = bV1;
        *reinterpret_cast<float4*>(&Bs[0][bk+8][bn4])  = bV2;
        *reinterpret_cast<float4*>(&Bs[0][bk+12][bn4]) = bV3;
    }
    __syncthreads();

    for (int t = 0; t < nk; t++) {
        int cur = t & 1;
        if (t + 1 < nk) {
            int k0 = k0base + (t + 1) * CBK;
            aR0 = *reinterpret_cast<const float4*>(arow + k0 + aq*8);
            aR1 = *reinterpret_cast<const float4*>(arow + k0 + aq*8 + 4);
            bV0 = *reinterpret_cast<const float4*>(Bm + (size_t)(k0 + bk)      * N + n0 + bn4);
            bV1 = *reinterpret_cast<const float4*>(Bm + (size_t)(k0 + bk + 4)  * N + n0 + bn4);
            bV2 = *reinterpret_cast<const float4*>(Bm + (size_t)(k0 + bk + 8)  * N + n0 + bn4);
            bV3 = *reinterpret_cast<const float4*>(Bm + (size_t)(k0 + bk + 12) * N + n0 + bn4);
        }
        #pragma unroll
        for (int kk = 0; kk < CBK; kk++) {
            float4 a0 = *reinterpret_cast<const float4*>(&As[cur][kk][fm]);
            float4 a1 = *reinterpret_cast<const float4*>(&As[cur][kk][fm + 32]);
            ulonglong2 bp0 = *reinterpret_cast<const ulonglong2*>(&Bs[cur][kk][fn]);
            ulonglong2 bp1 = *reinterpret_cast<const ulonglong2*>(&Bs[cur][kk][fn + 64]);
            unsigned long long bb[4] = {bp0.x, bp0.y, bp1.x, bp1.y};
            float a[8] = {a0.x, a0.y, a0.z, a0.w, a1.x, a1.y, a1.z, a1.w};
            #pragma unroll
            for (int i = 0; i < 8; i++) {
                unsigned long long ai = pk2(a[i], a[i]);
                #pragma unroll
                for (int j = 0; j < 4; j++)
                    fma2(acc2[i][j], ai, bb[j]);
            }
        }
        if (t + 1 < nk) {
            int nxt = cur ^ 1;
            int ab = aq*8;
            As[nxt][ab+0][am]=aR0.x; As[nxt][ab+1][am]=aR0.y; As[nxt][ab+2][am]=aR0.z; As[nxt][ab+3][am]=aR0.w;
            As[nxt][ab+4][am]=aR1.x; As[nxt][ab+5][am]=aR1.y; As[nxt][ab+6][am]=aR1.z; As[nxt][ab+7][am]=aR1.w;
            *reinterpret_cast<float4*>(&Bs[nxt][bk][bn4])    = bV0;
            *reinterpret_cast<float4*>(&Bs[nxt][bk+4][bn4])  = bV1;
            *reinterpret_cast<float4*>(&Bs[nxt][bk+8][bn4])  = bV2;
            *reinterpret_cast<float4*>(&Bs[nxt][bk+12][bn4]) = bV3;
        }
        __syncthreads();
    }

    float* outp = Cp + (size_t)z * 128 * N;
    #pragma unroll
    for (int i = 0; i < 8; i++) {
        int rm = m0 + (i < 4 ? fm + i : 32 + fm + (i - 4));
        float av[8];
        upk2(acc2[i][0], av[0], av[1]);
        upk2(acc2[i][1], av[2], av[3]);
        upk2(acc2[i][2], av[4], av[5]);
        upk2(acc2[i][3], av[6], av[7]);
        float4 s0 = make_float4(av[0], av[1], av[2], av[3]);
        float4 s1 = make_float4(av[4], av[5], av[6], av[7]);
        *reinterpret_cast<float4*>(&outp[(size_t)rm*N + n0 + fn     ]) = s0;
        *reinterpret_cast<float4*>(&outp[(size_t)rm*N + n0 + 64 + fn]) = s1;
    }
}

// sum split-K partials + bias + tanh
__global__ void fc_reduce_tanh(const float* __restrict__ part, const float* __restrict__ bias,
                               float* __restrict__ out, int MN, int N, int S)
{
    int idx = blockIdx.x * blockDim.x + threadIdx.x;
    if (idx >= MN) return;
    float s = 0.f;
    for (int i = 0; i < S; i++) s += part[(size_t)i * MN + idx];
    out[idx] = tanhf(s + bias[idx % N]);
}

// fc3: P[b][n] = sum_k H[b][k] * W[k][n] + bias[n]   (N=62)
__global__ void fc3_kernel(const float* __restrict__ H, const float* __restrict__ W,
                           const float* __restrict__ Bb, float* __restrict__ P)
{
    __shared__ float hs[2048];
    int b = blockIdx.x, tid = threadIdx.x;  // 64 threads
    for (int i = tid; i < 2048; i += 64) hs[i] = H[(size_t)b*2048 + i];
    __syncthreads();
    if (tid < 62) {
        float acc = Bb[tid];
        #pragma unroll 4
        for (int k = 0; k < 2048; k++) acc += hs[k] * W[(size_t)k*62 + tid];
        P[b*62 + tid] = acc;
    }
}

// trajectory assembly: out (128, 20*200, 2)
__global__ void traj_kernel(const float* __restrict__ P, const float* __restrict__ TD,
                            float* __restrict__ OUT)
{
    int b = blockIdx.x, tid = threadIdx.x;  // 256 threads
    __shared__ int   sidx[20];
    __shared__ float ssc[20][2];
    __shared__ float soff[20][2];
    __shared__ float sst[20][2];

    if (tid < 20) {
        float s0 = P[b*62 + 2 + tid*3];
        float s1 = P[b*62 + 3 + tid*3];
        float s2 = P[b*62 + 4 + tid*3];
        int idx = (int)fminf(fmaxf(rintf(s0), 0.f), 999.f);
        sidx[tid] = idx;
        ssc[tid][0] = s1; ssc[tid][1] = s2;
        soff[tid][0] = TD[idx*400 + 199*2 + 0] * s1;
        soff[tid][1] = TD[idx*400 + 199*2 + 1] * s2;
    }
    __syncthreads();
    if (tid == 0) {
        float cx = P[b*62 + 0], cy = P[b*62 + 1];
        for (int s = 0; s < 20; s++) {
            sst[s][0] = cx; sst[s][1] = cy;
            cx += soff[s][0]; cy += soff[s][1];
        }
    }
    __syncthreads();
    for (int e = tid; e < 20*200*2; e += 256) {
        int s = e / 400; int r = e - s*400;
        int c = r & 1;
        OUT[(size_t)b*8000 + e] = TD[sidx[s]*400 + r] * ssc[s][c] + sst[s][c];
    }
}

// ---------------------------------------------------------------------------
extern "C" void kernel_launch(void* const* d_in, const int* in_sizes, int n_in,
                              void* d_out, int out_size)
{
    const float* x   = (const float*)d_in[0];
    const float* w1  = (const float*)d_in[1];
    const float* b1  = (const float*)d_in[2];
    const float* w2  = (const float*)d_in[3];
    const float* b2  = (const float*)d_in[4];
    const float* w3  = (const float*)d_in[5];
    const float* b3  = (const float*)d_in[6];
    const float* w4  = (const float*)d_in[7];
    const float* b4  = (const float*)d_in[8];
    const float* fw1 = (const float*)d_in[9];
    const float* fb1 = (const float*)d_in[10];
    const float* fw2 = (const float*)d_in[11];
    const float* fb2 = (const float*)d_in[12];
    const float* fw3 = (const float*)d_in[13];
    const float* fb3 = (const float*)d_in[14];
    const float* td  = (const float*)d_in[15];

    float *h1, *c2, *h2, *c3, *h3, *c4, *h4, *p1, *f1, *p2, *f2, *pp;
    cudaGetSymbolAddress((void**)&h1, g_h1);
    cudaGetSymbolAddress((void**)&c2, g_c2);
    cudaGetSymbolAddress((void**)&h2, g_h2);
    cudaGetSymbolAddress((void**)&c3, g_c3);
    cudaGetSymbolAddress((void**)&h3, g_h3);
    cudaGetSymbolAddress((void**)&c4, g_c4);
    cudaGetSymbolAddress((void**)&h4, g_h4);
    cudaGetSymbolAddress((void**)&p1, g_part1);
    cudaGetSymbolAddress((void**)&f1, g_fc1);
    cudaGetSymbolAddress((void**)&p2, g_part2);
    cudaGetSymbolAddress((void**)&f2, g_fc2);
    cudaGetSymbolAddress((void**)&pp, g_p);

    // conv1 (fused pool+relu)
    conv1_pool<<<dim3(128, 7), 256>>>(x, w1, b1, h1);

    // conv2: M=128 (2 m-blocks), K=576, G=128 -> N=282752 = 2209 exact 128-tiles
    conv_gemm<<<dim3(2209, 2, 1), 128>>>(w2, h1, b2, c2, 128, 576, 64, 49, 49, 47, 47, 128);
    pool_relu<<<(8667136 + 255)/256, 256>>>(c2, h2, 47, 47, 23, 23, 8667136);

    // conv3: M=256 (4 m-blocks), K=1152, G=128 -> N=56448 = 441 exact tiles
    conv_gemm<<<dim3(441, 4, 1), 128>>>(w3, h2, b3, c3, 256, 1152, 128, 23, 23, 21, 21, 128);
    pool_relu<<<(3276800 + 255)/256, 256>>>(c3, h3, 21, 21, 10, 10, 3276800);

    // conv4: M=512 (8 m-blocks), K=2304, G=128 -> N=8192 = 64 exact tiles
    conv_gemm<<<dim3(64, 8, 1), 128>>>(w4, h3, b4, c4, 512, 2304, 256, 10, 10, 8, 8, 128);
    pool_relu<<<(1048576 + 255)/256, 256>>>(c4, h4, 8, 8, 4, 4, 1048576);

    // fc1: 128x8192 @ 8192x2048, split-K=16 (512 blocks)
    fc_gemm<<<dim3(16, 2, 16), 128>>>(h4, fw1, p1, 2048, 8192, 512);
    fc_reduce_tanh<<<(262144 + 255)/256, 256>>>(p1, fb1, f1, 262144, 2048, 16);

    // fc2: 128x2048 @ 2048x2048, split-K=8 (256 blocks)
    fc_gemm<<<dim3(16, 2, 8), 128>>>(f1, fw2, p2, 2048, 2048, 256);
    fc_reduce_tanh<<<(262144 + 255)/256, 256>>>(p2, fb2, f2, 262144, 2048, 8);

    // fc3: 2048 -> 62
    fc3_kernel<<<128, 64>>>(f2, fw3, fb3, pp);

    // trajectory assembly -> d_out (128*4000*2 floats)
    traj_kernel<<<128, 256>>>(pp, td, (float*)d_out);
}